// round 2
// baseline (speedup 1.0000x reference)
#include <cuda_runtime.h>
#include <math.h>
#include <stdint.h>

// ---------------------------------------------------------------------------
// SharedSpecialistMoEFFN — GB300 (sm_103a)
// Round 0: sparse top-2 expert execution + tf32 mma.sync GEMMs.
//
// Shapes: T=8192 tokens, D_MODEL=1024, D_FF=4096, N_EXP=8, TOP_K=2
// FLOPs: shared FFN (137 GF) + gathered expert rows 2T (275 GF) = 412 GFLOP
// ---------------------------------------------------------------------------

#define D_MODEL 1024
#define D_FF    4096
#define N_EXP   8
#define T_TOK   8192
#define MAX_BLOCKS 136                 // ceil padding: 16384/128 + 8
#define MAX_SLOTS  (MAX_BLOCKS * 128)  // 17408

// ---------------- scratch (device globals; no runtime allocation) ----------
__device__ float g_Hs[(size_t)T_TOK * D_FF];        // shared FFN hidden
__device__ float g_He[(size_t)MAX_SLOTS * D_FF];    // expert hidden (gathered)
__device__ float g_Ye[(size_t)MAX_SLOTS * D_MODEL]; // expert outputs (gathered)
__device__ int   g_perm[MAX_SLOTS];                 // slot -> token (-1 = pad)
__device__ int   g_topidx[T_TOK * 2];
__device__ float g_topw[T_TOK * 2];
__device__ int   g_slot[T_TOK * 2];                 // (token,k) -> slot
__device__ int   g_counts[N_EXP];
__device__ int   g_cursor[N_EXP];
__device__ int   g_offsets[N_EXP];
__device__ int   g_blk_expert[MAX_BLOCKS];
__device__ int   g_nblocks;

// ---------------- helpers ---------------------------------------------------
__device__ __forceinline__ float to_tf32(float x) {
    float r;
    asm("cvt.rna.tf32.f32 %0, %1;" : "=f"(r) : "f"(x));
    return r;
}

__device__ __forceinline__ void mma_tf32(float c[4], const unsigned a[4], const unsigned b[2]) {
    asm volatile(
        "mma.sync.aligned.m16n8k8.row.col.f32.tf32.tf32.f32 "
        "{%0,%1,%2,%3}, {%4,%5,%6,%7}, {%8,%9}, {%0,%1,%2,%3};\n"
        : "+f"(c[0]), "+f"(c[1]), "+f"(c[2]), "+f"(c[3])
        : "r"(a[0]), "r"(a[1]), "r"(a[2]), "r"(a[3]), "r"(b[0]), "r"(b[1]));
}

__device__ __forceinline__ float gelu_exact(float v) {
    return 0.5f * v * (1.0f + erff(v * 0.70710678118654752f));
}

// ---------------- init ------------------------------------------------------
__global__ void init_kernel() {
    int i = blockIdx.x * blockDim.x + threadIdx.x;
    if (i < MAX_SLOTS) g_perm[i] = -1;
    if (i < N_EXP) { g_counts[i] = 0; g_cursor[i] = 0; }
}

// ---------------- router: warp per token ------------------------------------
__global__ void router_kernel(const float* __restrict__ x,
                              const float* __restrict__ rw,
                              const float* __restrict__ rb) {
    int warp = threadIdx.x >> 5, lane = threadIdx.x & 31;
    int t = blockIdx.x * 8 + warp;
    const float* xr = x + (size_t)t * D_MODEL;
    float acc[8];
#pragma unroll
    for (int e = 0; e < 8; ++e) acc[e] = 0.f;
    for (int i = lane; i < D_MODEL; i += 32) {
        float xv = xr[i];
        const float4* r = (const float4*)(rw + (size_t)i * 8);
        float4 rA = r[0], rB = r[1];
        acc[0] += xv * rA.x; acc[1] += xv * rA.y;
        acc[2] += xv * rA.z; acc[3] += xv * rA.w;
        acc[4] += xv * rB.x; acc[5] += xv * rB.y;
        acc[6] += xv * rB.z; acc[7] += xv * rB.w;
    }
#pragma unroll
    for (int off = 16; off; off >>= 1)
#pragma unroll
        for (int e = 0; e < 8; ++e)
            acc[e] += __shfl_xor_sync(0xffffffffu, acc[e], off);
    if (lane == 0) {
        float l[8], m = -1e30f;
#pragma unroll
        for (int e = 0; e < 8; ++e) { l[e] = acc[e] + rb[e]; m = fmaxf(m, l[e]); }
        float p[8], Z = 0.f;
#pragma unroll
        for (int e = 0; e < 8; ++e) { p[e] = expf(l[e] - m); Z += p[e]; }
#pragma unroll
        for (int e = 0; e < 8; ++e) p[e] /= Z;
        // top-2 (ties -> lowest index, matching jax top_k)
        int i0 = 0;
#pragma unroll
        for (int e = 1; e < 8; ++e) if (p[e] > p[i0]) i0 = e;
        int i1 = (i0 == 0) ? 1 : 0;
#pragma unroll
        for (int e = 0; e < 8; ++e) if (e != i0 && p[e] > p[i1] && e != i1) {
            if (e < i1 || p[e] > p[i1]) i1 = e;
        }
        // (simpler exact pass)
        i1 = -1;
        for (int e = 0; e < 8; ++e) if (e != i0 && (i1 < 0 || p[e] > p[i1])) i1 = e;
        float s = p[i0] + p[i1] + 1e-9f;
        g_topidx[t * 2 + 0] = i0;
        g_topidx[t * 2 + 1] = i1;
        g_topw[t * 2 + 0] = p[i0] / s;
        g_topw[t * 2 + 1] = p[i1] / s;
        atomicAdd(&g_counts[i0], 1);
        atomicAdd(&g_counts[i1], 1);
    }
}

// ---------------- segment scan (tiny, single thread) -------------------------
__global__ void scan_kernel() {
    if (threadIdx.x == 0 && blockIdx.x == 0) {
        int tb = 0;
        for (int e = 0; e < N_EXP; ++e) {
            g_offsets[e] = tb * 128;
            int nb = (g_counts[e] + 127) >> 7;
            for (int b = 0; b < nb; ++b) g_blk_expert[tb + b] = e;
            tb += nb;
        }
        g_nblocks = tb;
    }
}

// ---------------- gather ----------------------------------------------------
__global__ void gather_kernel() {
    int t = blockIdx.x * blockDim.x + threadIdx.x;
    if (t >= T_TOK) return;
#pragma unroll
    for (int k = 0; k < 2; ++k) {
        int e = g_topidx[t * 2 + k];
        int pos = atomicAdd(&g_cursor[e], 1);
        int slot = g_offsets[e] + pos;
        g_perm[slot] = t;
        g_slot[t * 2 + k] = slot;
    }
}

// ---------------- tf32 GEMM: 128x128x16 tiles, 8 warps, m16n8k8 -------------
// C[M,N] = act(A[M,K] @ B[K,N] + bias), A row-major, B row-major.
// PERM: A rows gathered through g_perm (pad rows -> zeros).
// EXPERT: per-row-block expert weight/bias selection + early exit.
template <bool GELU, bool PERM, bool EXPERT>
__global__ __launch_bounds__(256, 2)
void gemm_tf32(const float* __restrict__ A, const float* __restrict__ Bw,
               const float* __restrict__ bias, float* __restrict__ C,
               int N, int K, long wstride, long bstride) {
    if (EXPERT) {
        if ((int)blockIdx.x >= g_nblocks) return;
        int e = g_blk_expert[blockIdx.x];
        Bw += (long)e * wstride;
        bias += (long)e * bstride;
    }
    __shared__ float As[2][16][132];
    __shared__ float Bs[2][16][132];

    const int tid = threadIdx.x;
    const int lane = tid & 31;
    const int warp = tid >> 5;
    const int wm = warp & 1;      // 2 warps along M -> 64 rows each
    const int wn = warp >> 1;     // 4 warps along N -> 32 cols each
    const int group = lane >> 2;  // 0..7
    const int quad = lane & 3;    // 0..3

    // loader mapping: A tile 128x16 (2 float4 per thread), B tile 16x128
    const int r0 = tid >> 2;      // 0..63
    const int kq = tid & 3;       // k-quad for A
    const int kr = tid >> 5;      // 0..7 for B
    const int n4 = tid & 31;      // float4 col for B

    long ga0, ga1;
    if (PERM) {
        ga0 = g_perm[blockIdx.x * 128 + r0];
        ga1 = g_perm[blockIdx.x * 128 + r0 + 64];
    } else {
        ga0 = (long)blockIdx.x * 128 + r0;
        ga1 = ga0 + 64;
    }
    const float* pA0 = (ga0 >= 0) ? A + (size_t)ga0 * K + kq * 4 : nullptr;
    const float* pA1 = (ga1 >= 0) ? A + (size_t)ga1 * K + kq * 4 : nullptr;
    const float* pB0 = Bw + (size_t)kr * N + (size_t)blockIdx.y * 128 + n4 * 4;
    const float* pB1 = pB0 + (size_t)8 * N;

    float c[4][4][4];
#pragma unroll
    for (int i = 0; i < 4; ++i)
#pragma unroll
        for (int j = 0; j < 4; ++j)
#pragma unroll
            for (int q = 0; q < 4; ++q) c[i][j][q] = 0.f;

    const int KT = K >> 4;
    float4 fa0, fa1, fb0, fb1;
    const float4 z4 = make_float4(0.f, 0.f, 0.f, 0.f);

    // prefetch tile 0
    fa0 = pA0 ? *(const float4*)(pA0) : z4;
    fa1 = pA1 ? *(const float4*)(pA1) : z4;
    fb0 = *(const float4*)(pB0);
    fb1 = *(const float4*)(pB1);
    // stage tile 0
    As[0][kq * 4 + 0][r0] = to_tf32(fa0.x);
    As[0][kq * 4 + 1][r0] = to_tf32(fa0.y);
    As[0][kq * 4 + 2][r0] = to_tf32(fa0.z);
    As[0][kq * 4 + 3][r0] = to_tf32(fa0.w);
    As[0][kq * 4 + 0][r0 + 64] = to_tf32(fa1.x);
    As[0][kq * 4 + 1][r0 + 64] = to_tf32(fa1.y);
    As[0][kq * 4 + 2][r0 + 64] = to_tf32(fa1.z);
    As[0][kq * 4 + 3][r0 + 64] = to_tf32(fa1.w);
    *(float4*)&Bs[0][kr][n4 * 4] =
        make_float4(to_tf32(fb0.x), to_tf32(fb0.y), to_tf32(fb0.z), to_tf32(fb0.w));
    *(float4*)&Bs[0][kr + 8][n4 * 4] =
        make_float4(to_tf32(fb1.x), to_tf32(fb1.y), to_tf32(fb1.z), to_tf32(fb1.w));
    __syncthreads();

    for (int kt = 0; kt < KT; ++kt) {
        const int buf = kt & 1;
        if (kt + 1 < KT) {
            size_t koff = (size_t)(kt + 1) * 16;
            fa0 = pA0 ? *(const float4*)(pA0 + koff) : z4;
            fa1 = pA1 ? *(const float4*)(pA1 + koff) : z4;
            fb0 = *(const float4*)(pB0 + koff * N);
            fb1 = *(const float4*)(pB1 + koff * N);
        }
#pragma unroll
        for (int s = 0; s < 2; ++s) {
            const int kb = s * 8;
            unsigned af[4][4], bf[4][2];
#pragma unroll
            for (int mi = 0; mi < 4; ++mi) {
                int m0 = wm * 64 + mi * 16 + group;
                af[mi][0] = __float_as_uint(As[buf][kb + quad][m0]);
                af[mi][1] = __float_as_uint(As[buf][kb + quad][m0 + 8]);
                af[mi][2] = __float_as_uint(As[buf][kb + quad + 4][m0]);
                af[mi][3] = __float_as_uint(As[buf][kb + quad + 4][m0 + 8]);
            }
#pragma unroll
            for (int ni = 0; ni < 4; ++ni) {
                int n0 = wn * 32 + ni * 8 + group;
                bf[ni][0] = __float_as_uint(Bs[buf][kb + quad][n0]);
                bf[ni][1] = __float_as_uint(Bs[buf][kb + quad + 4][n0]);
            }
#pragma unroll
            for (int mi = 0; mi < 4; ++mi)
#pragma unroll
                for (int ni = 0; ni < 4; ++ni)
                    mma_tf32(c[mi][ni], af[mi], bf[ni]);
        }
        if (kt + 1 < KT) {
            const int nb = buf ^ 1;
            As[nb][kq * 4 + 0][r0] = to_tf32(fa0.x);
            As[nb][kq * 4 + 1][r0] = to_tf32(fa0.y);
            As[nb][kq * 4 + 2][r0] = to_tf32(fa0.z);
            As[nb][kq * 4 + 3][r0] = to_tf32(fa0.w);
            As[nb][kq * 4 + 0][r0 + 64] = to_tf32(fa1.x);
            As[nb][kq * 4 + 1][r0 + 64] = to_tf32(fa1.y);
            As[nb][kq * 4 + 2][r0 + 64] = to_tf32(fa1.z);
            As[nb][kq * 4 + 3][r0 + 64] = to_tf32(fa1.w);
            *(float4*)&Bs[nb][kr][n4 * 4] =
                make_float4(to_tf32(fb0.x), to_tf32(fb0.y), to_tf32(fb0.z), to_tf32(fb0.w));
            *(float4*)&Bs[nb][kr + 8][n4 * 4] =
                make_float4(to_tf32(fb1.x), to_tf32(fb1.y), to_tf32(fb1.z), to_tf32(fb1.w));
        }
        __syncthreads();
    }

    // epilogue: bias (+gelu), write float2 pairs
#pragma unroll
    for (int mi = 0; mi < 4; ++mi) {
        int row = blockIdx.x * 128 + wm * 64 + mi * 16 + group;
#pragma unroll
        for (int ni = 0; ni < 4; ++ni) {
            int col = blockIdx.y * 128 + wn * 32 + ni * 8 + quad * 2;
            float bv0 = bias[col], bv1 = bias[col + 1];
            float v00 = c[mi][ni][0] + bv0;
            float v01 = c[mi][ni][1] + bv1;
            float v10 = c[mi][ni][2] + bv0;
            float v11 = c[mi][ni][3] + bv1;
            if (GELU) {
                v00 = gelu_exact(v00); v01 = gelu_exact(v01);
                v10 = gelu_exact(v10); v11 = gelu_exact(v11);
            }
            *(float2*)&C[(size_t)row * N + col] = make_float2(v00, v01);
            *(float2*)&C[(size_t)(row + 8) * N + col] = make_float2(v10, v11);
        }
    }
}

// ---------------- combine: out += w0*Ye[slot0] + w1*Ye[slot1] ---------------
__global__ void combine_kernel(float* __restrict__ out, const float* __restrict__ Ye) {
    int t = blockIdx.x;
    int col = threadIdx.x * 4;
    int s0 = g_slot[t * 2 + 0], s1 = g_slot[t * 2 + 1];
    float w0 = g_topw[t * 2 + 0], w1 = g_topw[t * 2 + 1];
    float4 o = *(const float4*)(out + (size_t)t * D_MODEL + col);
    float4 y0 = *(const float4*)(Ye + (size_t)s0 * D_MODEL + col);
    float4 y1 = *(const float4*)(Ye + (size_t)s1 * D_MODEL + col);
    o.x += w0 * y0.x + w1 * y1.x;
    o.y += w0 * y0.y + w1 * y1.y;
    o.z += w0 * y0.z + w1 * y1.z;
    o.w += w0 * y0.w + w1 * y1.w;
    *(float4*)(out + (size_t)t * D_MODEL + col) = o;
}

// ---------------- launch ----------------------------------------------------
extern "C" void kernel_launch(void* const* d_in, const int* in_sizes, int n_in,
                              void* d_out, int out_size) {
    const float* x   = (const float*)d_in[0];
    const float* sw1 = (const float*)d_in[1];
    const float* sb1 = (const float*)d_in[2];
    const float* sw2 = (const float*)d_in[3];
    const float* sb2 = (const float*)d_in[4];
    const float* rw  = (const float*)d_in[5];
    const float* rb  = (const float*)d_in[6];
    const float* ew1 = (const float*)d_in[7];
    const float* eb1 = (const float*)d_in[8];
    const float* ew2 = (const float*)d_in[9];
    const float* eb2 = (const float*)d_in[10];
    float* out = (float*)d_out;

    float *Hs, *He, *Ye;
    cudaGetSymbolAddress((void**)&Hs, g_Hs);
    cudaGetSymbolAddress((void**)&He, g_He);
    cudaGetSymbolAddress((void**)&Ye, g_Ye);

    init_kernel<<<(MAX_SLOTS + 255) / 256, 256>>>();
    router_kernel<<<T_TOK / 8, 256>>>(x, rw, rb);
    scan_kernel<<<1, 32>>>();
    gather_kernel<<<T_TOK / 256, 256>>>();

    // shared FFN
    gemm_tf32<true, false, false><<<dim3(T_TOK / 128, D_FF / 128), 256>>>(
        x, sw1, sb1, Hs, D_FF, D_MODEL, 0, 0);
    // expert FFN layer 1 (gathered rows)
    gemm_tf32<true, true, true><<<dim3(MAX_BLOCKS, D_FF / 128), 256>>>(
        x, ew1, eb1, He, D_FF, D_MODEL, (long)D_MODEL * D_FF, D_FF);
    // shared FFN layer 2 -> writes d_out fully
    gemm_tf32<false, false, false><<<dim3(T_TOK / 128, D_MODEL / 128), 256>>>(
        Hs, sw2, sb2, out, D_MODEL, D_FF, 0, 0);
    // expert FFN layer 2 (gathered rows)
    gemm_tf32<false, false, true><<<dim3(MAX_BLOCKS, D_MODEL / 128), 256>>>(
        He, ew2, eb2, Ye, D_MODEL, D_FF, (long)D_FF * D_MODEL, D_MODEL);

    combine_kernel<<<T_TOK, 256>>>(out, Ye);
}

// round 4
// speedup vs baseline: 3.2970x; 3.2970x over previous
#include <cuda_runtime.h>
#include <cuda_fp16.h>
#include <math.h>
#include <stdint.h>

// ---------------------------------------------------------------------------
// SharedSpecialistMoEFFN — GB300 (sm_103, legacy tensor path), Round 3
// fp16 mma.sync.m16n8k16 + ldmatrix + 4-stage cp.async. Sparse top-2 experts.
// ---------------------------------------------------------------------------

#define D_MODEL 1024
#define D_FF    4096
#define N_EXP   8
#define T_TOK   8192
#define MAX_BLOCKS 136
#define MAX_SLOTS  (MAX_BLOCKS * 128)

#define STAGES      4
#define A_STAGE     10240              // 128 rows * 80B (64B data + 16B pad)
#define B_STAGE     8192               // 32 rows * 256B
#define STAGE_BYTES (A_STAGE + B_STAGE)
#define SMEM_TOTAL  (STAGES * STAGE_BYTES)

// ---------------- scratch (device globals; zero runtime allocation) --------
__device__ __half g_xh[(size_t)T_TOK * D_MODEL];
__device__ __half g_w1h[(size_t)D_MODEL * D_FF];
__device__ __half g_w2h[(size_t)D_FF * D_MODEL];
__device__ __half g_ew1h[(size_t)N_EXP * D_MODEL * D_FF];
__device__ __half g_ew2h[(size_t)N_EXP * D_FF * D_MODEL];
__device__ __half g_Hsh[(size_t)T_TOK * D_FF];
__device__ __half g_Heh[(size_t)MAX_SLOTS * D_FF];
__device__ float  g_Ye[(size_t)MAX_SLOTS * D_MODEL];
__device__ int    g_perm[MAX_SLOTS];
__device__ int    g_topidx[T_TOK * 2];
__device__ float  g_topw[T_TOK * 2];
__device__ int    g_slot[T_TOK * 2];
__device__ int    g_counts[N_EXP];
__device__ int    g_cursor[N_EXP];
__device__ int    g_offsets[N_EXP];
__device__ int    g_blk_expert[MAX_BLOCKS];
__device__ int    g_nblocks;

// ---------------- helpers ---------------------------------------------------
__device__ __forceinline__ float gelu_exact(float v) {
    return 0.5f * v * (1.0f + erff(v * 0.70710678118654752f));
}
__device__ __forceinline__ uint32_t s2u(const void* p) {
    uint32_t a;
    asm("{ .reg .u64 t; cvta.to.shared.u64 t, %1; cvt.u32.u64 %0, t; }" : "=r"(a) : "l"(p));
    return a;
}
__device__ __forceinline__ void cp16(uint32_t dst, const void* src) {
    asm volatile("cp.async.cg.shared.global [%0], [%1], 16;" :: "r"(dst), "l"(src));
}
__device__ __forceinline__ void cp16s(uint32_t dst, const void* src, int sz) {
    asm volatile("cp.async.cg.shared.global [%0], [%1], 16, %2;"
                 :: "r"(dst), "l"(src), "r"(sz));
}
__device__ __forceinline__ void ldm_x4(uint32_t (&r)[4], uint32_t addr) {
    asm volatile("ldmatrix.sync.aligned.m8n8.x4.shared.b16 {%0,%1,%2,%3}, [%4];"
                 : "=r"(r[0]), "=r"(r[1]), "=r"(r[2]), "=r"(r[3]) : "r"(addr));
}
__device__ __forceinline__ void ldm_x4t(uint32_t (&r)[4], uint32_t addr) {
    asm volatile("ldmatrix.sync.aligned.m8n8.x4.trans.shared.b16 {%0,%1,%2,%3}, [%4];"
                 : "=r"(r[0]), "=r"(r[1]), "=r"(r[2]), "=r"(r[3]) : "r"(addr));
}
__device__ __forceinline__ void mma_f16(float c[4], const uint32_t a[4],
                                        uint32_t b0, uint32_t b1) {
    asm volatile(
        "mma.sync.aligned.m16n8k16.row.col.f32.f16.f16.f32 "
        "{%0,%1,%2,%3}, {%4,%5,%6,%7}, {%8,%9}, {%0,%1,%2,%3};\n"
        : "+f"(c[0]), "+f"(c[1]), "+f"(c[2]), "+f"(c[3])
        : "r"(a[0]), "r"(a[1]), "r"(a[2]), "r"(a[3]), "r"(b0), "r"(b1));
}

// ---------------- prep: fp32 -> fp16 ----------------------------------------
__global__ void f2h_kernel(const float* __restrict__ in, __half2* __restrict__ out) {
    size_t i = (size_t)blockIdx.x * blockDim.x + threadIdx.x;
    float4 v = ((const float4*)in)[i];
    out[i * 2 + 0] = __floats2half2_rn(v.x, v.y);
    out[i * 2 + 1] = __floats2half2_rn(v.z, v.w);
}

// ---------------- routing helpers -------------------------------------------
__global__ void init_kernel() {
    int i = blockIdx.x * blockDim.x + threadIdx.x;
    if (i < MAX_SLOTS) g_perm[i] = -1;
    if (i < N_EXP) { g_counts[i] = 0; g_cursor[i] = 0; }
}

__global__ void router_kernel(const float* __restrict__ x,
                              const float* __restrict__ rw,
                              const float* __restrict__ rb) {
    int warp = threadIdx.x >> 5, lane = threadIdx.x & 31;
    int t = blockIdx.x * 8 + warp;
    const float* xr = x + (size_t)t * D_MODEL;
    float acc[8];
#pragma unroll
    for (int e = 0; e < 8; ++e) acc[e] = 0.f;
    for (int i = lane; i < D_MODEL; i += 32) {
        float xv = xr[i];
        const float4* r = (const float4*)(rw + (size_t)i * 8);
        float4 rA = r[0], rB = r[1];
        acc[0] += xv * rA.x; acc[1] += xv * rA.y;
        acc[2] += xv * rA.z; acc[3] += xv * rA.w;
        acc[4] += xv * rB.x; acc[5] += xv * rB.y;
        acc[6] += xv * rB.z; acc[7] += xv * rB.w;
    }
#pragma unroll
    for (int off = 16; off; off >>= 1)
#pragma unroll
        for (int e = 0; e < 8; ++e)
            acc[e] += __shfl_xor_sync(0xffffffffu, acc[e], off);
    if (lane == 0) {
        float l[8], m = -1e30f;
#pragma unroll
        for (int e = 0; e < 8; ++e) { l[e] = acc[e] + rb[e]; m = fmaxf(m, l[e]); }
        float p[8], Z = 0.f;
#pragma unroll
        for (int e = 0; e < 8; ++e) { p[e] = expf(l[e] - m); Z += p[e]; }
#pragma unroll
        for (int e = 0; e < 8; ++e) p[e] /= Z;
        int i0 = 0;
#pragma unroll
        for (int e = 1; e < 8; ++e) if (p[e] > p[i0]) i0 = e;
        int i1 = -1;
        for (int e = 0; e < 8; ++e) if (e != i0 && (i1 < 0 || p[e] > p[i1])) i1 = e;
        float s = p[i0] + p[i1] + 1e-9f;
        g_topidx[t * 2 + 0] = i0;
        g_topidx[t * 2 + 1] = i1;
        g_topw[t * 2 + 0] = p[i0] / s;
        g_topw[t * 2 + 1] = p[i1] / s;
        atomicAdd(&g_counts[i0], 1);
        atomicAdd(&g_counts[i1], 1);
    }
}

__global__ void scan_kernel() {
    if (threadIdx.x == 0 && blockIdx.x == 0) {
        int tb = 0;
        for (int e = 0; e < N_EXP; ++e) {
            g_offsets[e] = tb * 128;
            int nb = (g_counts[e] + 127) >> 7;
            for (int b = 0; b < nb; ++b) g_blk_expert[tb + b] = e;
            tb += nb;
        }
        g_nblocks = tb;
    }
}

__global__ void gather_kernel() {
    int t = blockIdx.x * blockDim.x + threadIdx.x;
    if (t >= T_TOK) return;
#pragma unroll
    for (int k = 0; k < 2; ++k) {
        int e = g_topidx[t * 2 + k];
        int pos = atomicAdd(&g_cursor[e], 1);
        int slot = g_offsets[e] + pos;
        g_perm[slot] = t;
        g_slot[t * 2 + k] = slot;
    }
}

__global__ void combine_kernel(float* __restrict__ out, const float* __restrict__ Ye) {
    int t = blockIdx.x;
    int col = threadIdx.x * 4;
    int s0 = g_slot[t * 2 + 0], s1 = g_slot[t * 2 + 1];
    float w0 = g_topw[t * 2 + 0], w1 = g_topw[t * 2 + 1];
    float4 o = *(const float4*)(out + (size_t)t * D_MODEL + col);
    float4 y0 = *(const float4*)(Ye + (size_t)s0 * D_MODEL + col);
    float4 y1 = *(const float4*)(Ye + (size_t)s1 * D_MODEL + col);
    o.x += w0 * y0.x + w1 * y1.x;
    o.y += w0 * y0.y + w1 * y1.y;
    o.z += w0 * y0.z + w1 * y1.z;
    o.w += w0 * y0.w + w1 * y1.w;
    *(float4*)(out + (size_t)t * D_MODEL + col) = o;
}

// ---------------- fp16 GEMM --------------------------------------------------
// C[M,Ntot] = act(A[M,K] @ B[K,Ntot] + bias). A fp16 row-major, B fp16 row-major
// (k-major, loaded as col-major fragments via ldmatrix.trans). BM=BN=128, BK=32.
// PERM: A rows via g_perm (pad rows zero-filled). EXPERT: per-M-block expert.
// HALF_OUT: write fp16 (hidden), else fp32.
template <bool GELU, bool PERM, bool EXPERT, bool HALF_OUT>
__global__ __launch_bounds__(256, 2)
void gemm_h(const __half* __restrict__ A, const __half* __restrict__ Bw,
            const float* __restrict__ bias, void* __restrict__ Cv,
            int Ntot, int K, long wstride, long bstride) {
    int bm = blockIdx.x, bn = blockIdx.y;
    if (EXPERT) {
        if (bm >= g_nblocks) return;
        int e = g_blk_expert[bm];
        Bw += (long)e * wstride;
        bias += (long)e * bstride;
    }
    extern __shared__ char smem[];
    const uint32_t sb = s2u(smem);
    const int tid = threadIdx.x, lane = tid & 31, w = tid >> 5;
    const int wm = w & 1, wn = w >> 1;

    // --- loader setup: 2 A chunks + 2 B chunks per thread per stage ---------
    const __half* a_src[2]; uint32_t a_dst[2]; int a_sz[2];
#pragma unroll
    for (int i = 0; i < 2; ++i) {
        int c = tid + 256 * i, r = c >> 2, f = c & 3;
        a_dst[i] = (uint32_t)(r * 80 + f * 16);
        long row = PERM ? (long)g_perm[bm * 128 + r] : (long)bm * 128 + r;
        if (row >= 0) { a_src[i] = A + row * (long)K + f * 8; a_sz[i] = 16; }
        else          { a_src[i] = A;                          a_sz[i] = 0;  }
    }
    const __half* b_src[2]; uint32_t b_dst[2];
#pragma unroll
    for (int i = 0; i < 2; ++i) {
        int c = tid + 256 * i, k = c >> 4, j = c & 15;
        b_dst[i] = (uint32_t)(A_STAGE + k * 256 + (j ^ (k & 7)) * 16);
        b_src[i] = Bw + (long)k * Ntot + (long)bn * 128 + j * 8;
    }
    const long bKstep = (long)32 * Ntot;

    float acc[4][4][4];
#pragma unroll
    for (int i = 0; i < 4; ++i)
#pragma unroll
        for (int j = 0; j < 4; ++j)
#pragma unroll
            for (int q = 0; q < 4; ++q) acc[i][j][q] = 0.f;

    const int KT = K >> 5;

    // prologue: stages 0..2
#pragma unroll
    for (int p = 0; p < STAGES - 1; ++p) {
        uint32_t st = sb + p * STAGE_BYTES;
#pragma unroll
        for (int i = 0; i < 2; ++i) cp16s(st + a_dst[i], a_src[i] + (long)p * 32, a_sz[i]);
#pragma unroll
        for (int i = 0; i < 2; ++i) cp16(st + b_dst[i], b_src[i] + (long)p * bKstep);
        asm volatile("cp.async.commit_group;" ::: "memory");
    }

    // ldmatrix bases
    const uint32_t aBase = sb + (wm * 64 + (lane & 15)) * 80 + (lane >> 4) * 16;
    const uint32_t bBase = sb + A_STAGE + (((lane >> 3) & 1) * 8 + (lane & 7)) * 256;
    const uint32_t bCh0 = (uint32_t)(((wn * 4 + 0 + (lane >> 4)) ^ (lane & 7)) * 16);
    const uint32_t bCh1 = (uint32_t)(((wn * 4 + 2 + (lane >> 4)) ^ (lane & 7)) * 16);

    for (int kt = 0; kt < KT; ++kt) {
        asm volatile("cp.async.wait_group %0;" :: "n"(STAGES - 2) : "memory");
        __syncthreads();
        const uint32_t st = (uint32_t)((kt & 3) * STAGE_BYTES);
#pragma unroll
        for (int kk = 0; kk < 2; ++kk) {
            uint32_t af[4][4];
#pragma unroll
            for (int mi = 0; mi < 4; ++mi)
                ldm_x4(af[mi], aBase + st + mi * 16 * 80 + kk * 32);
            uint32_t bf0[4], bf1[4];
            ldm_x4t(bf0, bBase + st + kk * 16 * 256 + bCh0);
            ldm_x4t(bf1, bBase + st + kk * 16 * 256 + bCh1);
#pragma unroll
            for (int mi = 0; mi < 4; ++mi) {
                mma_f16(acc[mi][0], af[mi], bf0[0], bf0[1]);
                mma_f16(acc[mi][1], af[mi], bf0[2], bf0[3]);
                mma_f16(acc[mi][2], af[mi], bf1[0], bf1[1]);
                mma_f16(acc[mi][3], af[mi], bf1[2], bf1[3]);
            }
        }
        if (kt + STAGES - 1 < KT) {
            const int nx = kt + STAGES - 1;
            uint32_t st2 = sb + (nx & 3) * STAGE_BYTES;
#pragma unroll
            for (int i = 0; i < 2; ++i)
                cp16s(st2 + a_dst[i], a_src[i] + (long)nx * 32, a_sz[i]);
#pragma unroll
            for (int i = 0; i < 2; ++i)
                cp16(st2 + b_dst[i], b_src[i] + (long)nx * bKstep);
        }
        asm volatile("cp.async.commit_group;" ::: "memory");
    }

    // epilogue
#pragma unroll
    for (int mi = 0; mi < 4; ++mi) {
        int row = bm * 128 + wm * 64 + mi * 16 + (lane >> 2);
#pragma unroll
        for (int ni = 0; ni < 4; ++ni) {
            int col = bn * 128 + wn * 32 + ni * 8 + (lane & 3) * 2;
            float bv0 = bias[col], bv1 = bias[col + 1];
            float v00 = acc[mi][ni][0] + bv0;
            float v01 = acc[mi][ni][1] + bv1;
            float v10 = acc[mi][ni][2] + bv0;
            float v11 = acc[mi][ni][3] + bv1;
            if (GELU) {
                v00 = gelu_exact(v00); v01 = gelu_exact(v01);
                v10 = gelu_exact(v10); v11 = gelu_exact(v11);
            }
            if (HALF_OUT) {
                __half* C = (__half*)Cv;
                *(__half2*)&C[(size_t)row * Ntot + col] = __floats2half2_rn(v00, v01);
                *(__half2*)&C[(size_t)(row + 8) * Ntot + col] = __floats2half2_rn(v10, v11);
            } else {
                float* C = (float*)Cv;
                *(float2*)&C[(size_t)row * Ntot + col] = make_float2(v00, v01);
                *(float2*)&C[(size_t)(row + 8) * Ntot + col] = make_float2(v10, v11);
            }
        }
    }
}

// ---------------- launch ----------------------------------------------------
extern "C" void kernel_launch(void* const* d_in, const int* in_sizes, int n_in,
                              void* d_out, int out_size) {
    const float* x   = (const float*)d_in[0];
    const float* sw1 = (const float*)d_in[1];
    const float* sb1 = (const float*)d_in[2];
    const float* sw2 = (const float*)d_in[3];
    const float* sb2 = (const float*)d_in[4];
    const float* rw  = (const float*)d_in[5];
    const float* rb  = (const float*)d_in[6];
    const float* ew1 = (const float*)d_in[7];
    const float* eb1 = (const float*)d_in[8];
    const float* ew2 = (const float*)d_in[9];
    const float* eb2 = (const float*)d_in[10];
    float* out = (float*)d_out;

    __half *xh, *w1h, *w2h, *ew1h, *ew2h, *Hsh, *Heh;
    float* Ye;
    cudaGetSymbolAddress((void**)&xh, g_xh);
    cudaGetSymbolAddress((void**)&w1h, g_w1h);
    cudaGetSymbolAddress((void**)&w2h, g_w2h);
    cudaGetSymbolAddress((void**)&ew1h, g_ew1h);
    cudaGetSymbolAddress((void**)&ew2h, g_ew2h);
    cudaGetSymbolAddress((void**)&Hsh, g_Hsh);
    cudaGetSymbolAddress((void**)&Heh, g_Heh);
    cudaGetSymbolAddress((void**)&Ye, g_Ye);

    cudaFuncSetAttribute(gemm_h<true, false, false, true>,
                         cudaFuncAttributeMaxDynamicSharedMemorySize, SMEM_TOTAL);
    cudaFuncSetAttribute(gemm_h<true, true, true, true>,
                         cudaFuncAttributeMaxDynamicSharedMemorySize, SMEM_TOTAL);
    cudaFuncSetAttribute(gemm_h<false, false, false, false>,
                         cudaFuncAttributeMaxDynamicSharedMemorySize, SMEM_TOTAL);
    cudaFuncSetAttribute(gemm_h<false, false, true, false>,
                         cudaFuncAttributeMaxDynamicSharedMemorySize, SMEM_TOTAL);

    // fp32 -> fp16 conversions
    f2h_kernel<<<(T_TOK * D_MODEL / 4) / 256, 256>>>(x, (__half2*)xh);
    f2h_kernel<<<(D_MODEL * D_FF / 4) / 256, 256>>>(sw1, (__half2*)w1h);
    f2h_kernel<<<(D_FF * D_MODEL / 4) / 256, 256>>>(sw2, (__half2*)w2h);
    f2h_kernel<<<(N_EXP * D_MODEL * D_FF / 4) / 256, 256>>>(ew1, (__half2*)ew1h);
    f2h_kernel<<<(N_EXP * D_FF * D_MODEL / 4) / 256, 256>>>(ew2, (__half2*)ew2h);

    init_kernel<<<(MAX_SLOTS + 255) / 256, 256>>>();
    router_kernel<<<T_TOK / 8, 256>>>(x, rw, rb);
    scan_kernel<<<1, 32>>>();
    gather_kernel<<<T_TOK / 256, 256>>>();

    // shared FFN layer 1: Hsh = gelu(xh @ w1 + b1)  (fp16 out)
    gemm_h<true, false, false, true><<<dim3(T_TOK / 128, D_FF / 128), 256, SMEM_TOTAL>>>(
        xh, w1h, sb1, Hsh, D_FF, D_MODEL, 0, 0);
    // expert layer 1 (gathered): Heh = gelu(xh[perm] @ ew1[e] + eb1[e])
    gemm_h<true, true, true, true><<<dim3(MAX_BLOCKS, D_FF / 128), 256, SMEM_TOTAL>>>(
        xh, ew1h, eb1, Heh, D_FF, D_MODEL, (long)D_MODEL * D_FF, D_FF);
    // shared FFN layer 2 -> d_out (fp32, full overwrite)
    gemm_h<false, false, false, false><<<dim3(T_TOK / 128, D_MODEL / 128), 256, SMEM_TOTAL>>>(
        Hsh, w2h, sb2, out, D_MODEL, D_FF, 0, 0);
    // expert layer 2: Ye = Heh @ ew2[e] + eb2[e]  (fp32)
    gemm_h<false, false, true, false><<<dim3(MAX_BLOCKS, D_MODEL / 128), 256, SMEM_TOTAL>>>(
        Heh, ew2h, eb2, Ye, D_MODEL, D_FF, (long)D_FF * D_MODEL, D_MODEL);

    combine_kernel<<<T_TOK, 256>>>(out, Ye);
}